// round 1
// baseline (speedup 1.0000x reference)
#include <cuda_runtime.h>
#include <cuda_bf16.h>
#include <cstdint>

// Output: [32, 4096, 1024] fp32. Value depends only on column:
//   out[..., c] = coef  if (c odd && c < 1022)  else 0
// Row of 1024 floats = 256 float4s. Every float4 is (0, coef, 0, coef)
// except the last one per row (cols 1020..1023) which is (0, coef, 0, 0).

static constexpr long long TOTAL_FLOATS = 32LL * 4096LL * 1024LL;   // 134,217,728
static constexpr long long TOTAL_VEC4   = TOTAL_FLOATS / 4;         // 33,554,432
static constexpr int       VEC4_PER_ROW = 1024 / 4;                 // 256

__global__ void posenc_fill_kernel(float4* __restrict__ out,
                                   const float* __restrict__ coef_ptr) {
    const float coef = __ldg(coef_ptr);
    const float4 body = make_float4(0.0f, coef, 0.0f, coef);
    const float4 tail = make_float4(0.0f, coef, 0.0f, 0.0f);

    long long i = (long long)blockIdx.x * blockDim.x + threadIdx.x;
    const long long stride = (long long)gridDim.x * blockDim.x;
    for (; i < TOTAL_VEC4; i += stride) {
        // position of this float4 within its 1024-float row
        const int col4 = (int)(i & (VEC4_PER_ROW - 1));
        out[i] = (col4 == VEC4_PER_ROW - 1) ? tail : body;
    }
}

extern "C" void kernel_launch(void* const* d_in, const int* in_sizes, int n_in,
                              void* d_out, int out_size) {
    // coef_param is the LAST input per setup_inputs ordering
    const float* coef = (const float*)d_in[n_in - 1];
    float4* out = (float4*)d_out;

    const int threads = 256;
    // one float4 per thread per iteration; launch enough blocks to cover all
    // vec4s in a single pass (grid-stride loop handles any mismatch)
    long long blocks_ll = (TOTAL_VEC4 + threads - 1) / threads;
    int blocks = (blocks_ll > 1048576LL) ? 1048576 : (int)blocks_ll;

    posenc_fill_kernel<<<blocks, threads>>>(out, coef);
}

// round 2
// speedup vs baseline: 1.4058x; 1.4058x over previous
#include <cuda_runtime.h>
#include <cuda_bf16.h>
#include <cstdint>

// Output: [32, 4096, 1024] fp32. out[..., c] = coef if (c odd && c < 1022) else 0.
// Row = 1024 floats = 256 float4s; all float4s are (0,coef,0,coef) except the
// last float4 of each row which is (0,coef,0,0).
//
// Layout: blockDim=256, each thread stores VEC_PER_THREAD float4s at stride
// 256 float4s (one blockDim). Since block base is a multiple of 256, the
// within-row float4 index of every store by thread t is exactly t. So only
// tid==255 ever writes the row-tail float4 -> value is a per-thread constant.

static constexpr long long TOTAL_VEC4     = 32LL * 4096LL * 1024LL / 4;  // 33,554,432
static constexpr int       THREADS        = 256;
static constexpr int       VEC_PER_THREAD = 16;
static constexpr int       VEC_PER_BLOCK  = THREADS * VEC_PER_THREAD;    // 4096
static constexpr int       BLOCKS         = (int)(TOTAL_VEC4 / VEC_PER_BLOCK); // 8192

__global__ __launch_bounds__(THREADS)
void posenc_fill_kernel(float4* __restrict__ out,
                        const float* __restrict__ coef_ptr) {
    const float coef = __ldg(coef_ptr);
    // tid==255 is the only lane that ever lands on a row's last float4
    const float w3 = (threadIdx.x == THREADS - 1) ? 0.0f : coef;
    const float4 val = make_float4(0.0f, coef, 0.0f, w3);

    float4* p = out + (long long)blockIdx.x * VEC_PER_BLOCK + threadIdx.x;
#pragma unroll
    for (int k = 0; k < VEC_PER_THREAD; ++k) {
        p[k * THREADS] = val;   // immediate byte offset k*4096 in STG.E.128
    }
}

extern "C" void kernel_launch(void* const* d_in, const int* in_sizes, int n_in,
                              void* d_out, int out_size) {
    const float* coef = (const float*)d_in[n_in - 1];  // coef_param is last input
    posenc_fill_kernel<<<BLOCKS, THREADS>>>((float4*)d_out, coef);
}